// round 6
// baseline (speedup 1.0000x reference)
#include <cuda_runtime.h>
#include <cuda_bf16.h>
#include <cuda_fp8.h>
#include <math.h>
#include <stdint.h>

#define NTOK   8192
#define DMODEL 2048
#define DFF    2048
#define NEXP   8
#define NASSIGN (NTOK*2)
#define MAXTILES 136
#define PADROWS 128
#define AMAX_BLOCKS 1184

// ---------------- device scratch ----------------
__device__ float    g_bmax[AMAX_BLOCKS];
__device__ float    g_scale_x;
__device__ int      g_offset[NEXP+1];
__device__ int      g_eid[NASSIGN];
__device__ float    g_cw[NASSIGN];
__device__ int      g_list[NASSIGN];
__device__ int      g_pos[NASSIGN];

__device__ __align__(16) uint8_t       g_xq8 [(size_t)NTOK*DMODEL];                  // 16 MB (e4m3)
__device__ __align__(16) uint8_t       g_w13q8[(size_t)NEXP*2*DFF*DMODEL];           // 67 MB (e4m3)
__device__ __align__(16) __nv_bfloat16 g_w2 [(size_t)NEXP*DMODEL*DFF];               // 67 MB
__device__ __align__(16) __nv_bfloat16 g_hhi[(size_t)(NASSIGN+PADROWS)*DFF];
__device__ __align__(16) __nv_bfloat16 g_hlo[(size_t)(NASSIGN+PADROWS)*DFF];
__device__ __align__(16) float         g_part[(size_t)(NASSIGN+PADROWS)*DMODEL];

// ---------------- PTX helpers ----------------
__device__ __forceinline__ unsigned smem_u32(const void* p) {
    return (unsigned)__cvta_generic_to_shared(p);
}
__device__ __forceinline__ void cpasync16(unsigned dst, const void* src) {
    asm volatile("cp.async.cg.shared.global [%0], [%1], 16;"::"r"(dst),"l"(src):"memory");
}
__device__ __forceinline__ void cpasync16z(unsigned dst, const void* src, int sz) {
    asm volatile("cp.async.cg.shared.global [%0], [%1], 16, %2;"::"r"(dst),"l"(src),"r"(sz):"memory");
}
#define CP_COMMIT() asm volatile("cp.async.commit_group;":::"memory")
#define CP_WAIT1()  asm volatile("cp.async.wait_group 1;":::"memory")
#define CP_WAIT0()  asm volatile("cp.async.wait_group 0;":::"memory")

__device__ __forceinline__ void ldsm4(unsigned& r0, unsigned& r1, unsigned& r2, unsigned& r3,
                                      unsigned addr) {
    asm volatile("ldmatrix.sync.aligned.m8n8.x4.shared.b16 {%0,%1,%2,%3}, [%4];"
                 : "=r"(r0), "=r"(r1), "=r"(r2), "=r"(r3) : "r"(addr));
}
__device__ __forceinline__ void mma16816(float* d, const unsigned* a, unsigned b0, unsigned b1) {
    asm volatile(
        "mma.sync.aligned.m16n8k16.row.col.f32.bf16.bf16.f32 "
        "{%0,%1,%2,%3}, {%4,%5,%6,%7}, {%8,%9}, {%0,%1,%2,%3};"
        : "+f"(d[0]), "+f"(d[1]), "+f"(d[2]), "+f"(d[3])
        : "r"(a[0]), "r"(a[1]), "r"(a[2]), "r"(a[3]), "r"(b0), "r"(b1));
}
__device__ __forceinline__ void mma16832f8(float* d, const unsigned* a, unsigned b0, unsigned b1) {
    asm volatile(
        "mma.sync.aligned.m16n8k32.row.col.f32.e4m3.e4m3.f32 "
        "{%0,%1,%2,%3}, {%4,%5,%6,%7}, {%8,%9}, {%0,%1,%2,%3};"
        : "+f"(d[0]), "+f"(d[1]), "+f"(d[2]), "+f"(d[3])
        : "r"(a[0]), "r"(a[1]), "r"(a[2]), "r"(a[3]), "r"(b0), "r"(b1));
}
__device__ __forceinline__ unsigned sw128(unsigned off) { return off ^ ((off >> 3) & 0x70); }
__device__ __forceinline__ unsigned ldsm_addr(unsigned tile_base, int row, int half, int kk) {
    unsigned within = (unsigned)(half*16 + kk*32);
    return tile_base + (unsigned)row*128u + (within ^ (((unsigned)row & 7u) << 4));
}
__device__ __forceinline__ unsigned pack_bf2(float a, float b) {
    __nv_bfloat16 x = __float2bfloat16(a), y = __float2bfloat16(b);
    return (unsigned)*(unsigned short*)&x | ((unsigned)*(unsigned short*)&y << 16);
}
__device__ __forceinline__ unsigned pack_fp8x4(float a, float b, float c, float d) {
    __nv_fp8x4_e4m3 q(make_float4(a, b, c, d));
    return *(unsigned*)&q;
}

// decode block slot -> (expert, row_base, rows) from g_offset
__device__ __forceinline__ bool decode_slot(int slot, int& e, int& row_base, int& rows) {
    int off0 = g_offset[0];
    #pragma unroll
    for (int ee = 0; ee < NEXP; ee++) {
        int off1 = g_offset[ee+1];
        int cnt = off1 - off0;
        int nt = (cnt + 127) >> 7;
        if (slot < nt) {
            e = ee; row_base = off0 + slot*128; rows = min(128, cnt - slot*128);
            return true;
        }
        slot -= nt; off0 = off1;
    }
    return false;
}

// ---------------- launch 0: per-block amax (no atomics, no zeroing needed) ----------------
__global__ void k_amax(const float4* __restrict__ x, int n4) {
    float m = 0.f;
    int stride = gridDim.x*blockDim.x;
    int i = blockIdx.x*blockDim.x + threadIdx.x;
    for (; i + 3*stride < n4; i += 4*stride) {
        float4 v0 = x[i], v1 = x[i+stride], v2 = x[i+2*stride], v3 = x[i+3*stride];
        m = fmaxf(m, fmaxf(fmaxf(fabsf(v0.x),fabsf(v0.y)),fmaxf(fabsf(v0.z),fabsf(v0.w))));
        m = fmaxf(m, fmaxf(fmaxf(fabsf(v1.x),fabsf(v1.y)),fmaxf(fabsf(v1.z),fabsf(v1.w))));
        m = fmaxf(m, fmaxf(fmaxf(fabsf(v2.x),fabsf(v2.y)),fmaxf(fabsf(v2.z),fabsf(v2.w))));
        m = fmaxf(m, fmaxf(fmaxf(fabsf(v3.x),fabsf(v3.y)),fmaxf(fabsf(v3.z),fabsf(v3.w))));
    }
    for (; i < n4; i += stride) {
        float4 v = x[i];
        m = fmaxf(m, fmaxf(fmaxf(fabsf(v.x),fabsf(v.y)),fmaxf(fabsf(v.z),fabsf(v.w))));
    }
    for (int o = 16; o; o >>= 1) m = fmaxf(m, __shfl_xor_sync(0xffffffffu, m, o));
    __shared__ float sm[8];
    if ((threadIdx.x & 31) == 0) sm[threadIdx.x >> 5] = m;
    __syncthreads();
    if (threadIdx.x < 8) {
        float v = sm[threadIdx.x];
        for (int o = 4; o; o >>= 1) v = fmaxf(v, __shfl_xor_sync(0xffu, v, o));
        if (threadIdx.x == 0) g_bmax[blockIdx.x] = v;
    }
}

// ---------------- launch 1: reduce bmax -> scale; quantize x -> e4m3 ----------------
__global__ void k_quant(const float4* __restrict__ x4, int n16) {
    __shared__ float s_scale;
    {
        float m = 0.f;
        for (int i = threadIdx.x; i < AMAX_BLOCKS; i += blockDim.x) m = fmaxf(m, g_bmax[i]);
        for (int o = 16; o; o >>= 1) m = fmaxf(m, __shfl_xor_sync(0xffffffffu, m, o));
        __shared__ float sm[8];
        if ((threadIdx.x & 31) == 0) sm[threadIdx.x >> 5] = m;
        __syncthreads();
        if (threadIdx.x == 0) {
            float v = sm[0];
            #pragma unroll
            for (int w = 1; w < 8; w++) v = fmaxf(v, sm[w]);
            float s = fmaxf(v, 1e-12f) / 448.0f;
            s_scale = s;
            if (blockIdx.x == 0) g_scale_x = s;
        }
        __syncthreads();
    }
    float inv = 1.0f / s_scale;
    uint4* dst = (uint4*)g_xq8;
    int stride = gridDim.x*blockDim.x;
    for (int i = blockIdx.x*blockDim.x + threadIdx.x; i < n16; i += stride) {
        float4 a = x4[4*i], b = x4[4*i+1], c = x4[4*i+2], d = x4[4*i+3];
        uint4 o;
        o.x = pack_fp8x4(a.x*inv, a.y*inv, a.z*inv, a.w*inv);
        o.y = pack_fp8x4(b.x*inv, b.y*inv, b.z*inv, b.w*inv);
        o.z = pack_fp8x4(c.x*inv, c.y*inv, c.z*inv, c.w*inv);
        o.w = pack_fp8x4(d.x*inv, d.y*inv, d.z*inv, d.w*inv);
        dst[i] = o;
    }
}

// ---------------- launch 2: fused w13 cvt + w2 cvt + route/scatter ----------------
#define CVT13_BLK 1024
#define CVT2_BLK  1024
#define FUSE_GRID (CVT13_BLK + CVT2_BLK + 1)

__global__ void k_fuse(const float* __restrict__ gating,
                       const float4* __restrict__ w13q,
                       const float4* __restrict__ w2q) {
    int b = blockIdx.x;
    int tid = threadIdx.x;
    if (b < CVT13_BLK) {
        // w13 fp32 (exact e4m3 codes) -> e4m3 bytes
        const int n16 = NEXP*2*DFF*DMODEL/16;
        uint4* dst = (uint4*)g_w13q8;
        int stride = CVT13_BLK*blockDim.x;
        for (int i = b*blockDim.x + tid; i < n16; i += stride) {
            float4 a = w13q[4*i], bb = w13q[4*i+1], c = w13q[4*i+2], d = w13q[4*i+3];
            uint4 o;
            o.x = pack_fp8x4(a.x, a.y, a.z, a.w);
            o.y = pack_fp8x4(bb.x, bb.y, bb.z, bb.w);
            o.z = pack_fp8x4(c.x, c.y, c.z, c.w);
            o.w = pack_fp8x4(d.x, d.y, d.z, d.w);
            dst[i] = o;
        }
    } else if (b < CVT13_BLK + CVT2_BLK) {
        // w2 fp32 -> bf16
        const int n8 = NEXP*DMODEL*DFF/8;
        uint4* dst = (uint4*)g_w2;
        int bb2 = b - CVT13_BLK;
        int stride = CVT2_BLK*blockDim.x;
        for (int i = bb2*blockDim.x + tid; i < n8; i += stride) {
            float4 a = w2q[2*i], c = w2q[2*i+1];
            uint4 o;
            o.x = pack_bf2(a.x, a.y);
            o.y = pack_bf2(a.z, a.w);
            o.z = pack_bf2(c.x, c.y);
            o.w = pack_bf2(c.z, c.w);
            dst[i] = o;
        }
    } else {
        // single block: route (softmax top-2) + counts + offsets + scatter
        __shared__ int cnt[NEXP], off[NEXP+1], cur[NEXP];
        if (tid < NEXP) { cnt[tid] = 0; cur[tid] = 0; }
        __syncthreads();
        for (int t = tid; t < NTOK; t += blockDim.x) {
            float g[NEXP];
            #pragma unroll
            for (int e = 0; e < NEXP; e++) g[e] = gating[t*NEXP + e];
            int i0 = 0; float b0 = g[0];
            #pragma unroll
            for (int e = 1; e < NEXP; e++) if (g[e] > b0) { b0 = g[e]; i0 = e; }
            int i1 = -1; float b1 = -INFINITY;
            #pragma unroll
            for (int e = 0; e < NEXP; e++) if (e != i0 && g[e] > b1) { b1 = g[e]; i1 = e; }
            float r  = expf(b1 - b0);
            float w0 = 1.f / (1.f + r);
            float w1 = r  / (1.f + r);
            g_eid[2*t]   = i0; g_cw[2*t]   = w0;
            g_eid[2*t+1] = i1; g_cw[2*t+1] = w1;
            atomicAdd(&cnt[i0], 1);
            atomicAdd(&cnt[i1], 1);
        }
        __syncthreads();
        if (tid == 0) {
            int o = 0;
            #pragma unroll
            for (int e = 0; e < NEXP; e++) { off[e] = o; g_offset[e] = o; o += cnt[e]; }
            off[NEXP] = o; g_offset[NEXP] = o;
        }
        __syncthreads();
        for (int a = tid; a < NASSIGN; a += blockDim.x) {
            int e = g_eid[a];
            int p = off[e] + atomicAdd(&cur[e], 1);
            g_list[p] = a;
            g_pos[a] = p;
        }
    }
}

// ================= GEMM1 (fp8 e4m3) — launch 3 (profiled) =================
#define G1_STG  49152
#define G1_BOFF 16384
#define G1_SMEM (3*G1_STG)      // 144 KB
#define G1_PITCH 136

__device__ __forceinline__ void g1_fill(unsigned sbase, const int* s_tok, const uint8_t* wb,
                                        int cg, int kc, int buf, int tid) {
    int k0 = kc * 128;
    unsigned st = sbase + (unsigned)buf * G1_STG;
    #pragma unroll
    for (int i = 0; i < 2; i++) {
        int idx = tid + i*512;
        int r = idx >> 3, c = idx & 7;
        int tok = s_tok[r];
        unsigned dst = st + sw128((unsigned)(r*128 + c*16));
        const void* src = g_xq8 + ((size_t)(tok < 0 ? 0 : tok) * DMODEL + k0 + c*16);
        cpasync16z(dst, src, tok < 0 ? 0 : 16);
    }
    #pragma unroll
    for (int i = 0; i < 4; i++) {
        int idx = tid + i*512;
        int r = idx >> 3, c = idx & 7;
        int wrow = cg*128 + (r & 127) + ((r >> 7) ? DFF : 0);
        unsigned dst = st + G1_BOFF + sw128((unsigned)(r*128 + c*16));
        cpasync16(dst, wb + (size_t)wrow*DMODEL + k0 + c*16);
    }
}

__global__ __launch_bounds__(512,1) void k_gemm1(const float* __restrict__ w13_scale) {
    int e, row_base, rows;
    if (!decode_slot(blockIdx.y, e, row_base, rows)) return;
    int cg = blockIdx.x;

    extern __shared__ char smc[];
    __shared__ int s_tok[128];
    unsigned sbase = smem_u32(smc);
    int tid  = threadIdx.x;
    int wid  = tid >> 5, lane = tid & 31;
    int m0   = (wid & 3) * 32;
    int n0   = (wid >> 2) * 32;
    const uint8_t* wb = g_w13q8 + (size_t)e * 2*DFF*DMODEL;

    if (tid < 128) s_tok[tid] = (tid < rows) ? (g_list[row_base + tid] >> 1) : -1;
    __syncthreads();

    g1_fill(sbase, s_tok, wb, cg, 0, 0, tid); CP_COMMIT();
    g1_fill(sbase, s_tok, wb, cg, 1, 1, tid); CP_COMMIT();

    float acc[2][8][4];
    #pragma unroll
    for (int a = 0; a < 2; a++)
        #pragma unroll
        for (int b = 0; b < 8; b++)
            #pragma unroll
            for (int c = 0; c < 4; c++) acc[a][b][c] = 0.f;

    int arow = lane & 15, ahalf = lane >> 4;
    const int NT = DMODEL / 128;
    for (int kt = 0; kt < NT; kt++) {
        if (kt + 2 < NT) { CP_WAIT1(); } else { CP_WAIT0(); }
        __syncthreads();
        if (kt + 2 < NT) { g1_fill(sbase, s_tok, wb, cg, kt+2, (kt+2)%3, tid); CP_COMMIT(); }

        unsigned st = sbase + (unsigned)(kt % 3) * G1_STG;
        #pragma unroll
        for (int kk = 0; kk < 4; kk++) {
            unsigned af[2][4];
            #pragma unroll
            for (int mi = 0; mi < 2; mi++)
                ldsm4(af[mi][0], af[mi][1], af[mi][2], af[mi][3],
                      ldsm_addr(st, m0 + mi*16 + arow, ahalf, kk));
            #pragma unroll
            for (int side = 0; side < 2; side++) {
                #pragma unroll
                for (int nf = 0; nf < 2; nf++) {
                    unsigned b0, b1, b2, b3;
                    int brow = side*128 + n0 + nf*16 + arow;
                    ldsm4(b0, b1, b2, b3, ldsm_addr(st + G1_BOFF, brow, ahalf, kk));
                    #pragma unroll
                    for (int mi = 0; mi < 2; mi++) {
                        mma16832f8(acc[mi][side*4 + nf*2 + 0], af[mi], b0, b2);
                        mma16832f8(acc[mi][side*4 + nf*2 + 1], af[mi], b1, b3);
                    }
                }
            }
        }
    }

    __syncthreads();
    float sc = g_scale_x * __ldg(w13_scale + e);
    __nv_bfloat16* shi = (__nv_bfloat16*)smc;
    __nv_bfloat16* slo = shi + 128*G1_PITCH;
    int qrow = lane >> 2, qc2 = (lane & 3) * 2;
    #pragma unroll
    for (int mi = 0; mi < 2; mi++)
        #pragma unroll
        for (int half = 0; half < 2; half++) {
            int r = m0 + mi*16 + half*8 + qrow;
            int ei = half*2;
            #pragma unroll
            for (int j = 0; j < 4; j++) {
                float g0 = acc[mi][j][ei]     * sc;
                float g1 = acc[mi][j][ei+1]   * sc;
                float u0 = acc[mi][4+j][ei]   * sc;
                float u1 = acc[mi][4+j][ei+1] * sc;
                float h0 = (g0 / (1.f + expf(-g0))) * u0;
                float h1 = (g1 / (1.f + expf(-g1))) * u1;
                __nv_bfloat16 a0 = __float2bfloat16(h0), a1 = __float2bfloat16(h1);
                float l0 = h0 - __bfloat162float(a0);
                float l1 = h1 - __bfloat162float(a1);
                int col = n0 + j*8 + qc2;
                *(unsigned*)(shi + r*G1_PITCH + col) =
                    (unsigned)*(unsigned short*)&a0 | ((unsigned)*(unsigned short*)&a1 << 16);
                *(unsigned*)(slo + r*G1_PITCH + col) = pack_bf2(l0, l1);
            }
        }
    __syncthreads();
    #pragma unroll
    for (int it = 0; it < 4; it++) {
        int i = tid + it*512;
        int r = i >> 4, c = i & 15;
        if (r < rows) {
            size_t off = (size_t)(row_base + r) * DFF + (size_t)cg*128 + c*8;
            *(uint4*)(g_hhi + off) = *(const uint4*)(shi + r*G1_PITCH + c*8);
            *(uint4*)(g_hlo + off) = *(const uint4*)(slo + r*G1_PITCH + c*8);
        }
    }
}

// ================= GEMM2 (bf16 hi/lo) — launch 4 =================
#define G2_STG   65536
#define G2_ALOFF 16384
#define G2_BOFF  32768
#define G2_SMEM  (3*G2_STG)     // 192 KB
#define G2_PITCH 260

__device__ __forceinline__ void g2_fill(unsigned sbase, int row_base, const __nv_bfloat16* wb,
                                        int cgo, int kc, int buf, int tid) {
    int k0 = kc * 64;
    unsigned st = sbase + (unsigned)buf * G2_STG;
    #pragma unroll
    for (int i = 0; i < 2; i++) {
        int idx = tid + i*512;
        int r = idx >> 3, c = idx & 7;
        unsigned swo = sw128((unsigned)(r*128 + c*16));
        size_t off = (size_t)(row_base + r) * DFF + k0 + c*8;
        cpasync16(st + swo,            g_hhi + off);
        cpasync16(st + G2_ALOFF + swo, g_hlo + off);
    }
    #pragma unroll
    for (int i = 0; i < 4; i++) {
        int idx = tid + i*512;
        int r = idx >> 3, c = idx & 7;
        int n = cgo*256 + r;
        unsigned dst = st + G2_BOFF + sw128((unsigned)(r*128 + c*16));
        cpasync16(dst, wb + (size_t)n*DFF + k0 + c*8);
    }
}

__global__ __launch_bounds__(512,1) void k_gemm2(const float* __restrict__ w2_scale) {
    int e, row_base, rows;
    if (!decode_slot(blockIdx.y, e, row_base, rows)) return;
    int cgo = blockIdx.x;

    extern __shared__ char smc[];
    unsigned sbase = smem_u32(smc);
    int tid  = threadIdx.x;
    int wid  = tid >> 5, lane = tid & 31;
    int m0   = (wid & 3) * 32;
    int n0   = (wid >> 2) * 64;
    const __nv_bfloat16* wb = g_w2 + (size_t)e * DMODEL * DFF;

    g2_fill(sbase, row_base, wb, cgo, 0, 0, tid); CP_COMMIT();
    g2_fill(sbase, row_base, wb, cgo, 1, 1, tid); CP_COMMIT();

    float acc[2][8][4];
    #pragma unroll
    for (int a = 0; a < 2; a++)
        #pragma unroll
        for (int b = 0; b < 8; b++)
            #pragma unroll
            for (int c = 0; c < 4; c++) acc[a][b][c] = 0.f;

    int arow = lane & 15, ahalf = lane >> 4;
    const int NT = DFF / 64;
    for (int kt = 0; kt < NT; kt++) {
        if (kt + 2 < NT) { CP_WAIT1(); } else { CP_WAIT0(); }
        __syncthreads();
        if (kt + 2 < NT) { g2_fill(sbase, row_base, wb, cgo, kt+2, (kt+2)%3, tid); CP_COMMIT(); }

        unsigned st = sbase + (unsigned)(kt % 3) * G2_STG;
        #pragma unroll
        for (int kk = 0; kk < 4; kk++) {
            unsigned ah[2][4], al[2][4];
            #pragma unroll
            for (int mi = 0; mi < 2; mi++) {
                ldsm4(ah[mi][0], ah[mi][1], ah[mi][2], ah[mi][3],
                      ldsm_addr(st,            m0 + mi*16 + arow, ahalf, kk));
                ldsm4(al[mi][0], al[mi][1], al[mi][2], al[mi][3],
                      ldsm_addr(st + G2_ALOFF, m0 + mi*16 + arow, ahalf, kk));
            }
            #pragma unroll
            for (int nf = 0; nf < 4; nf++) {
                unsigned b0, b1, b2, b3;
                int brow = n0 + nf*16 + arow;
                ldsm4(b0, b1, b2, b3, ldsm_addr(st + G2_BOFF, brow, ahalf, kk));
                #pragma unroll
                for (int mi = 0; mi < 2; mi++) {
                    mma16816(acc[mi][nf*2 + 0], ah[mi], b0, b2);
                    mma16816(acc[mi][nf*2 + 0], al[mi], b0, b2);
                    mma16816(acc[mi][nf*2 + 1], ah[mi], b1, b3);
                    mma16816(acc[mi][nf*2 + 1], al[mi], b1, b3);
                }
            }
        }
    }

    __syncthreads();
    float sc = __ldg(w2_scale + e);
    float* sC = (float*)smc;
    int qrow = lane >> 2, qc2 = (lane & 3) * 2;
    #pragma unroll
    for (int mi = 0; mi < 2; mi++)
        #pragma unroll
        for (int half = 0; half < 2; half++) {
            int r = m0 + mi*16 + half*8 + qrow;
            int ei = half*2;
            #pragma unroll
            for (int j = 0; j < 8; j++) {
                float2 v;
                v.x = acc[mi][j][ei]   * sc;
                v.y = acc[mi][j][ei+1] * sc;
                *(float2*)(sC + r*G2_PITCH + n0 + j*8 + qc2) = v;
            }
        }
    __syncthreads();
    #pragma unroll
    for (int it = 0; it < 16; it++) {
        int i = tid + it*512;
        int r = i >> 6, c = i & 63;
        if (r < rows) {
            *(float4*)(g_part + (size_t)(row_base + r) * DMODEL + (size_t)cgo*256 + c*4) =
                *(const float4*)(sC + r*G2_PITCH + c*4);
        }
    }
}

// ---------------- launch 5: combine ----------------
__global__ void k_combine(float* __restrict__ out) {
    const int n4 = NTOK*DMODEL/4;
    const float4* part4 = (const float4*)g_part;
    int stride = gridDim.x*blockDim.x;
    int i = blockIdx.x*blockDim.x + threadIdx.x;
    for (; i + stride < n4; i += 2*stride) {
        #pragma unroll
        for (int u = 0; u < 2; u++) {
            int j = i + u*stride;
            int t  = j >> 9;
            int c4 = j & 511;
            float w0 = g_cw[2*t], w1 = g_cw[2*t+1];
            int p0 = g_pos[2*t], p1 = g_pos[2*t+1];
            float4 a = part4[(size_t)p0*512 + c4];
            float4 b = part4[(size_t)p1*512 + c4];
            float4 o;
            o.x = w0*a.x + w1*b.x;
            o.y = w0*a.y + w1*b.y;
            o.z = w0*a.z + w1*b.z;
            o.w = w0*a.w + w1*b.w;
            ((float4*)out)[j] = o;
        }
    }
    for (; i < n4; i += stride) {
        int t  = i >> 9;
        int c4 = i & 511;
        float w0 = g_cw[2*t], w1 = g_cw[2*t+1];
        int p0 = g_pos[2*t], p1 = g_pos[2*t+1];
        float4 a = part4[(size_t)p0*512 + c4];
        float4 b = part4[(size_t)p1*512 + c4];
        float4 o;
        o.x = w0*a.x + w1*b.x;
        o.y = w0*a.y + w1*b.y;
        o.z = w0*a.z + w1*b.z;
        o.w = w0*a.w + w1*b.w;
        ((float4*)out)[i] = o;
    }
}

// ---------------- launch ----------------
extern "C" void kernel_launch(void* const* d_in, const int* in_sizes, int n_in,
                              void* d_out, int out_size) {
    const float* x      = (const float*)d_in[0];
    const float* gating = (const float*)d_in[1];
    const float* w13q   = (const float*)d_in[2];
    const float* w13s   = (const float*)d_in[3];
    const float* w2q    = (const float*)d_in[4];
    const float* w2s    = (const float*)d_in[5];
    float* out = (float*)d_out;

    cudaFuncSetAttribute(k_gemm1, cudaFuncAttributeMaxDynamicSharedMemorySize, G1_SMEM);
    cudaFuncSetAttribute(k_gemm2, cudaFuncAttributeMaxDynamicSharedMemorySize, G2_SMEM);

    k_amax<<<AMAX_BLOCKS, 256>>>((const float4*)x, NTOK*DMODEL/4);
    k_quant<<<512, 256>>>((const float4*)x, NTOK*DMODEL/16);
    k_fuse<<<FUSE_GRID, 256>>>(gating, (const float4*)w13q, (const float4*)w2q);

    dim3 gg1(16, MAXTILES);
    k_gemm1<<<gg1, 512, G1_SMEM>>>(w13s);          // launch index 3 -> profiled
    dim3 gg2(8, MAXTILES);
    k_gemm2<<<gg2, 512, G2_SMEM>>>(w2s);

    k_combine<<<1184, 256>>>(out);
}

// round 8
// speedup vs baseline: 1.3187x; 1.3187x over previous
#include <cuda_runtime.h>
#include <cuda_bf16.h>
#include <cuda_fp16.h>
#include <cuda_fp8.h>
#include <math.h>
#include <stdint.h>

// R8 == R7 resubmit: infra failure last round, design unevaluated.
// GEMM1: fp8 e4m3 mma, 256thr/CTA, 2 CTAs/SM. GEMM2: fp16 single-pass.

#define NTOK   8192
#define DMODEL 2048
#define DFF    2048
#define NEXP   8
#define NASSIGN (NTOK*2)
#define MAXTILES 136
#define PADROWS 128
#define AMAX_BLOCKS 1184

// ---------------- device scratch ----------------
__device__ float    g_bmax[AMAX_BLOCKS];
__device__ float    g_scale_x;
__device__ int      g_offset[NEXP+1];
__device__ int      g_eid[NASSIGN];
__device__ float    g_cw[NASSIGN];
__device__ int      g_list[NASSIGN];
__device__ int      g_pos[NASSIGN];

__device__ __align__(16) uint8_t g_xq8  [(size_t)NTOK*DMODEL];                 // 16 MB e4m3
__device__ __align__(16) uint8_t g_w13q8[(size_t)NEXP*2*DFF*DMODEL];           // 67 MB e4m3
__device__ __align__(16) __half  g_w2h  [(size_t)NEXP*DMODEL*DFF];             // 67 MB fp16 (exact)
__device__ __align__(16) __half  g_h    [(size_t)(NASSIGN+PADROWS)*DFF];       // 67 MB fp16
__device__ __align__(16) float   g_part [(size_t)(NASSIGN+PADROWS)*DMODEL];    // 135 MB

// ---------------- PTX helpers ----------------
__device__ __forceinline__ unsigned smem_u32(const void* p) {
    return (unsigned)__cvta_generic_to_shared(p);
}
__device__ __forceinline__ void cpasync16(unsigned dst, const void* src) {
    asm volatile("cp.async.cg.shared.global [%0], [%1], 16;"::"r"(dst),"l"(src):"memory");
}
__device__ __forceinline__ void cpasync16z(unsigned dst, const void* src, int sz) {
    asm volatile("cp.async.cg.shared.global [%0], [%1], 16, %2;"::"r"(dst),"l"(src),"r"(sz):"memory");
}
#define CP_COMMIT() asm volatile("cp.async.commit_group;":::"memory")
#define CP_WAIT1()  asm volatile("cp.async.wait_group 1;":::"memory")
#define CP_WAIT0()  asm volatile("cp.async.wait_group 0;":::"memory")

__device__ __forceinline__ void ldsm4(unsigned& r0, unsigned& r1, unsigned& r2, unsigned& r3,
                                      unsigned addr) {
    asm volatile("ldmatrix.sync.aligned.m8n8.x4.shared.b16 {%0,%1,%2,%3}, [%4];"
                 : "=r"(r0), "=r"(r1), "=r"(r2), "=r"(r3) : "r"(addr));
}
__device__ __forceinline__ void mma16816h(float* d, const unsigned* a, unsigned b0, unsigned b1) {
    asm volatile(
        "mma.sync.aligned.m16n8k16.row.col.f32.f16.f16.f32 "
        "{%0,%1,%2,%3}, {%4,%5,%6,%7}, {%8,%9}, {%0,%1,%2,%3};"
        : "+f"(d[0]), "+f"(d[1]), "+f"(d[2]), "+f"(d[3])
        : "r"(a[0]), "r"(a[1]), "r"(a[2]), "r"(a[3]), "r"(b0), "r"(b1));
}
__device__ __forceinline__ void mma16832f8(float* d, const unsigned* a, unsigned b0, unsigned b1) {
    asm volatile(
        "mma.sync.aligned.m16n8k32.row.col.f32.e4m3.e4m3.f32 "
        "{%0,%1,%2,%3}, {%4,%5,%6,%7}, {%8,%9}, {%0,%1,%2,%3};"
        : "+f"(d[0]), "+f"(d[1]), "+f"(d[2]), "+f"(d[3])
        : "r"(a[0]), "r"(a[1]), "r"(a[2]), "r"(a[3]), "r"(b0), "r"(b1));
}
__device__ __forceinline__ unsigned sw128(unsigned off) { return off ^ ((off >> 3) & 0x70); }
__device__ __forceinline__ unsigned ldsm_addr(unsigned tile_base, int row, int half, int kk) {
    unsigned within = (unsigned)(half*16 + kk*32);
    return tile_base + (unsigned)row*128u + (within ^ (((unsigned)row & 7u) << 4));
}
__device__ __forceinline__ unsigned pack_h2(float a, float b) {
    __half x = __float2half_rn(a), y = __float2half_rn(b);
    return (unsigned)*(unsigned short*)&x | ((unsigned)*(unsigned short*)&y << 16);
}
__device__ __forceinline__ unsigned pack_fp8x4(float a, float b, float c, float d) {
    __nv_fp8x4_e4m3 q(make_float4(a, b, c, d));
    return *(unsigned*)&q;
}

// decode block slot -> (expert, row_base, rows)
__device__ __forceinline__ bool decode_slot(int slot, int& e, int& row_base, int& rows) {
    int off0 = g_offset[0];
    #pragma unroll
    for (int ee = 0; ee < NEXP; ee++) {
        int off1 = g_offset[ee+1];
        int cnt = off1 - off0;
        int nt = (cnt + 127) >> 7;
        if (slot < nt) {
            e = ee; row_base = off0 + slot*128; rows = min(128, cnt - slot*128);
            return true;
        }
        slot -= nt; off0 = off1;
    }
    return false;
}

// ---------------- launch 0: per-block amax ----------------
__global__ void k_amax(const float4* __restrict__ x, int n4) {
    float m = 0.f;
    int stride = gridDim.x*blockDim.x;
    int i = blockIdx.x*blockDim.x + threadIdx.x;
    for (; i + 3*stride < n4; i += 4*stride) {
        float4 v0 = x[i], v1 = x[i+stride], v2 = x[i+2*stride], v3 = x[i+3*stride];
        m = fmaxf(m, fmaxf(fmaxf(fabsf(v0.x),fabsf(v0.y)),fmaxf(fabsf(v0.z),fabsf(v0.w))));
        m = fmaxf(m, fmaxf(fmaxf(fabsf(v1.x),fabsf(v1.y)),fmaxf(fabsf(v1.z),fabsf(v1.w))));
        m = fmaxf(m, fmaxf(fmaxf(fabsf(v2.x),fabsf(v2.y)),fmaxf(fabsf(v2.z),fabsf(v2.w))));
        m = fmaxf(m, fmaxf(fmaxf(fabsf(v3.x),fabsf(v3.y)),fmaxf(fabsf(v3.z),fabsf(v3.w))));
    }
    for (; i < n4; i += stride) {
        float4 v = x[i];
        m = fmaxf(m, fmaxf(fmaxf(fabsf(v.x),fabsf(v.y)),fmaxf(fabsf(v.z),fabsf(v.w))));
    }
    for (int o = 16; o; o >>= 1) m = fmaxf(m, __shfl_xor_sync(0xffffffffu, m, o));
    __shared__ float sm[8];
    if ((threadIdx.x & 31) == 0) sm[threadIdx.x >> 5] = m;
    __syncthreads();
    if (threadIdx.x < 8) {
        float v = sm[threadIdx.x];
        for (int o = 4; o; o >>= 1) v = fmaxf(v, __shfl_xor_sync(0xffu, v, o));
        if (threadIdx.x == 0) g_bmax[blockIdx.x] = v;
    }
}

// ---------------- launch 1: scale + quantize x ----------------
__global__ void k_quant(const float4* __restrict__ x4, int n16) {
    __shared__ float s_scale;
    {
        float m = 0.f;
        for (int i = threadIdx.x; i < AMAX_BLOCKS; i += blockDim.x) m = fmaxf(m, g_bmax[i]);
        for (int o = 16; o; o >>= 1) m = fmaxf(m, __shfl_xor_sync(0xffffffffu, m, o));
        __shared__ float sm[8];
        if ((threadIdx.x & 31) == 0) sm[threadIdx.x >> 5] = m;
        __syncthreads();
        if (threadIdx.x == 0) {
            float v = sm[0];
            #pragma unroll
            for (int w = 1; w < 8; w++) v = fmaxf(v, sm[w]);
            float s = fmaxf(v, 1e-12f) / 448.0f;
            s_scale = s;
            if (blockIdx.x == 0) g_scale_x = s;
        }
        __syncthreads();
    }
    float inv = 1.0f / s_scale;
    uint4* dst = (uint4*)g_xq8;
    int stride = gridDim.x*blockDim.x;
    for (int i = blockIdx.x*blockDim.x + threadIdx.x; i < n16; i += stride) {
        float4 a = x4[4*i], b = x4[4*i+1], c = x4[4*i+2], d = x4[4*i+3];
        uint4 o;
        o.x = pack_fp8x4(a.x*inv, a.y*inv, a.z*inv, a.w*inv);
        o.y = pack_fp8x4(b.x*inv, b.y*inv, b.z*inv, b.w*inv);
        o.z = pack_fp8x4(c.x*inv, c.y*inv, c.z*inv, c.w*inv);
        o.w = pack_fp8x4(d.x*inv, d.y*inv, d.z*inv, d.w*inv);
        dst[i] = o;
    }
}

// ---------------- launch 2: fused w13 cvt + w2 cvt + route/scatter ----------------
#define CVT13_BLK 1024
#define CVT2_BLK  1024
#define FUSE_GRID (CVT13_BLK + CVT2_BLK + 1)

__global__ void k_fuse(const float* __restrict__ gating,
                       const float4* __restrict__ w13q,
                       const float4* __restrict__ w2q) {
    int b = blockIdx.x;
    int tid = threadIdx.x;
    if (b < CVT13_BLK) {
        const int n16 = NEXP*2*DFF*DMODEL/16;
        uint4* dst = (uint4*)g_w13q8;
        int stride = CVT13_BLK*blockDim.x;
        for (int i = b*blockDim.x + tid; i < n16; i += stride) {
            float4 a = w13q[4*i], bb = w13q[4*i+1], c = w13q[4*i+2], d = w13q[4*i+3];
            uint4 o;
            o.x = pack_fp8x4(a.x, a.y, a.z, a.w);
            o.y = pack_fp8x4(bb.x, bb.y, bb.z, bb.w);
            o.z = pack_fp8x4(c.x, c.y, c.z, c.w);
            o.w = pack_fp8x4(d.x, d.y, d.z, d.w);
            dst[i] = o;
        }
    } else if (b < CVT13_BLK + CVT2_BLK) {
        const int n8 = NEXP*DMODEL*DFF/8;
        uint4* dst = (uint4*)g_w2h;
        int bb2 = b - CVT13_BLK;
        int stride = CVT2_BLK*blockDim.x;
        for (int i = bb2*blockDim.x + tid; i < n8; i += stride) {
            float4 a = w2q[2*i], c = w2q[2*i+1];
            uint4 o;
            o.x = pack_h2(a.x, a.y);
            o.y = pack_h2(a.z, a.w);
            o.z = pack_h2(c.x, c.y);
            o.w = pack_h2(c.z, c.w);
            dst[i] = o;
        }
    } else {
        __shared__ int cnt[NEXP], off[NEXP+1], cur[NEXP];
        if (tid < NEXP) { cnt[tid] = 0; cur[tid] = 0; }
        __syncthreads();
        for (int t = tid; t < NTOK; t += blockDim.x) {
            float g[NEXP];
            #pragma unroll
            for (int e = 0; e < NEXP; e++) g[e] = gating[t*NEXP + e];
            int i0 = 0; float b0 = g[0];
            #pragma unroll
            for (int e = 1; e < NEXP; e++) if (g[e] > b0) { b0 = g[e]; i0 = e; }
            int i1 = -1; float b1 = -INFINITY;
            #pragma unroll
            for (int e = 0; e < NEXP; e++) if (e != i0 && g[e] > b1) { b1 = g[e]; i1 = e; }
            float r  = expf(b1 - b0);
            float w0 = 1.f / (1.f + r);
            float w1 = r  / (1.f + r);
            g_eid[2*t]   = i0; g_cw[2*t]   = w0;
            g_eid[2*t+1] = i1; g_cw[2*t+1] = w1;
            atomicAdd(&cnt[i0], 1);
            atomicAdd(&cnt[i1], 1);
        }
        __syncthreads();
        if (tid == 0) {
            int o = 0;
            #pragma unroll
            for (int e = 0; e < NEXP; e++) { off[e] = o; g_offset[e] = o; o += cnt[e]; }
            off[NEXP] = o; g_offset[NEXP] = o;
        }
        __syncthreads();
        for (int a = tid; a < NASSIGN; a += blockDim.x) {
            int e = g_eid[a];
            int p = off[e] + atomicAdd(&cur[e], 1);
            g_list[p] = a;
            g_pos[a] = p;
        }
    }
}

// ================= GEMM1 (fp8) — 256 thr, 2 CTAs/SM, tile M128 x (64g+64u) =================
#define G1_STG  32768           // A 16KB + B 16KB
#define G1_BOFF 16384
#define G1_SMEM (3*G1_STG)      // 96 KB
#define G1_PITCH 72             // halves; 144B row pitch

__device__ __forceinline__ void g1_fill(unsigned sbase, const int* s_tok, const uint8_t* wb,
                                        int cg, int kc, int buf, int tid) {
    int k0 = kc * 128;
    unsigned st = sbase + (unsigned)buf * G1_STG;
    #pragma unroll
    for (int i = 0; i < 4; i++) {                 // A: 128 rows x 8 x 16B fp8
        int idx = tid + i*256;
        int r = idx >> 3, c = idx & 7;
        int tok = s_tok[r];
        unsigned dst = st + sw128((unsigned)(r*128 + c*16));
        const void* src = g_xq8 + ((size_t)(tok < 0 ? 0 : tok) * DMODEL + k0 + c*16);
        cpasync16z(dst, src, tok < 0 ? 0 : 16);
    }
    #pragma unroll
    for (int i = 0; i < 4; i++) {                 // B: 64 gate rows + 64 up rows
        int idx = tid + i*256;
        int rr = idx >> 3, c = idx & 7;
        int wrow = cg*64 + (rr & 63) + ((rr >> 6) ? DFF : 0);
        unsigned dst = st + G1_BOFF + sw128((unsigned)(rr*128 + c*16));
        cpasync16(dst, wb + (size_t)wrow*DMODEL + k0 + c*16);
    }
}

__global__ __launch_bounds__(256,2) void k_gemm1(const float* __restrict__ w13_scale) {
    int e, row_base, rows;
    if (!decode_slot(blockIdx.y, e, row_base, rows)) return;
    int cg = blockIdx.x;                           // 0..31 -> 64 gate cols

    extern __shared__ char smc[];
    __shared__ int s_tok[128];
    unsigned sbase = smem_u32(smc);
    int tid  = threadIdx.x;
    int wid  = tid >> 5, lane = tid & 31;
    int m0   = (wid & 3) * 32;
    int n0   = (wid >> 2) * 32;                    // 0 or 32 within 64-col group
    const uint8_t* wb = g_w13q8 + (size_t)e * 2*DFF*DMODEL;

    if (tid < 128) s_tok[tid] = (tid < rows) ? (g_list[row_base + tid] >> 1) : -1;
    __syncthreads();

    g1_fill(sbase, s_tok, wb, cg, 0, 0, tid); CP_COMMIT();
    g1_fill(sbase, s_tok, wb, cg, 1, 1, tid); CP_COMMIT();

    float acc[2][8][4];                            // [mi][0-3 gate,4-7 up][4]
    #pragma unroll
    for (int a = 0; a < 2; a++)
        #pragma unroll
        for (int b = 0; b < 8; b++)
            #pragma unroll
            for (int c = 0; c < 4; c++) acc[a][b][c] = 0.f;

    int arow = lane & 15, ahalf = lane >> 4;
    const int NT = DMODEL / 128;                   // 16
    for (int kt = 0; kt < NT; kt++) {
        if (kt + 2 < NT) { CP_WAIT1(); } else { CP_WAIT0(); }
        __syncthreads();
        if (kt + 2 < NT) { g1_fill(sbase, s_tok, wb, cg, kt+2, (kt+2)%3, tid); CP_COMMIT(); }

        unsigned st = sbase + (unsigned)(kt % 3) * G1_STG;
        #pragma unroll
        for (int kk = 0; kk < 4; kk++) {
            unsigned af[2][4];
            #pragma unroll
            for (int mi = 0; mi < 2; mi++)
                ldsm4(af[mi][0], af[mi][1], af[mi][2], af[mi][3],
                      ldsm_addr(st, m0 + mi*16 + arow, ahalf, kk));
            #pragma unroll
            for (int side = 0; side < 2; side++) {    // 0=gate rows 0-63, 1=up rows 64-127
                #pragma unroll
                for (int nf = 0; nf < 2; nf++) {
                    unsigned b0, b1, b2, b3;
                    int brow = side*64 + n0 + nf*16 + arow;
                    ldsm4(b0, b1, b2, b3, ldsm_addr(st + G1_BOFF, brow, ahalf, kk));
                    #pragma unroll
                    for (int mi = 0; mi < 2; mi++) {
                        mma16832f8(acc[mi][side*4 + nf*2 + 0], af[mi], b0, b2);
                        mma16832f8(acc[mi][side*4 + nf*2 + 1], af[mi], b1, b3);
                    }
                }
            }
        }
    }

    // epilogue: silu(gate)*up -> fp16, stage via smem, coalesced store
    __syncthreads();
    float sc = g_scale_x * __ldg(w13_scale + e);
    __half* sh = (__half*)smc;
    int qrow = lane >> 2, qc2 = (lane & 3) * 2;
    #pragma unroll
    for (int mi = 0; mi < 2; mi++)
        #pragma unroll
        for (int half = 0; half < 2; half++) {
            int r = m0 + mi*16 + half*8 + qrow;
            int ei = half*2;
            #pragma unroll
            for (int j = 0; j < 4; j++) {
                float g0 = acc[mi][j][ei]     * sc;
                float g1 = acc[mi][j][ei+1]   * sc;
                float u0 = acc[mi][4+j][ei]   * sc;
                float u1 = acc[mi][4+j][ei+1] * sc;
                float h0 = (g0 / (1.f + expf(-g0))) * u0;
                float h1 = (g1 / (1.f + expf(-g1))) * u1;
                int col = n0 + j*8 + qc2;
                *(unsigned*)(sh + r*G1_PITCH + col) = pack_h2(h0, h1);
            }
        }
    __syncthreads();
    #pragma unroll
    for (int it = 0; it < 4; it++) {
        int i = tid + it*256;
        int r = i >> 3, c = i & 7;
        if (r < rows) {
            *(uint4*)(g_h + (size_t)(row_base + r) * DFF + (size_t)cg*64 + c*8) =
                *(const uint4*)(sh + r*G1_PITCH + c*8);
        }
    }
}

// ================= GEMM2 (fp16 single-pass) — 256 thr, 2 CTAs/SM, tile M128 x N128 ============
#define G2_STG  32768           // A 16KB + B 16KB (both fp16, K-stage 64)
#define G2_BOFF 16384
#define G2_SMEM (3*G2_STG)      // 96 KB
#define G2_PITCH 132            // floats

__device__ __forceinline__ void g2_fill(unsigned sbase, int row_base, const __half* wb,
                                        int cgo, int kc, int buf, int tid) {
    int k0 = kc * 64;
    unsigned st = sbase + (unsigned)buf * G2_STG;
    #pragma unroll
    for (int i = 0; i < 4; i++) {                 // A: 128 rows x 8 x 16B
        int idx = tid + i*256;
        int r = idx >> 3, c = idx & 7;
        unsigned dst = st + sw128((unsigned)(r*128 + c*16));
        cpasync16(dst, g_h + (size_t)(row_base + r) * DFF + k0 + c*8);
    }
    #pragma unroll
    for (int i = 0; i < 4; i++) {                 // B: 128 rows x 8 x 16B
        int idx = tid + i*256;
        int rr = idx >> 3, c = idx & 7;
        int n = cgo*128 + rr;
        unsigned dst = st + G2_BOFF + sw128((unsigned)(rr*128 + c*16));
        cpasync16(dst, wb + (size_t)n*DFF + k0 + c*8);
    }
}

__global__ __launch_bounds__(256,2) void k_gemm2(const float* __restrict__ w2_scale) {
    int e, row_base, rows;
    if (!decode_slot(blockIdx.y, e, row_base, rows)) return;
    int cgo = blockIdx.x;                          // 0..15 -> 128 out cols

    extern __shared__ char smc[];
    unsigned sbase = smem_u32(smc);
    int tid  = threadIdx.x;
    int wid  = tid >> 5, lane = tid & 31;
    int m0   = (wid & 3) * 32;
    int n0   = (wid >> 2) * 64;                    // 0 or 64
    const __half* wb = g_w2h + (size_t)e * DMODEL * DFF;

    g2_fill(sbase, row_base, wb, cgo, 0, 0, tid); CP_COMMIT();
    g2_fill(sbase, row_base, wb, cgo, 1, 1, tid); CP_COMMIT();

    float acc[2][8][4];
    #pragma unroll
    for (int a = 0; a < 2; a++)
        #pragma unroll
        for (int b = 0; b < 8; b++)
            #pragma unroll
            for (int c = 0; c < 4; c++) acc[a][b][c] = 0.f;

    int arow = lane & 15, ahalf = lane >> 4;
    const int NT = DFF / 64;                       // 32
    for (int kt = 0; kt < NT; kt++) {
        if (kt + 2 < NT) { CP_WAIT1(); } else { CP_WAIT0(); }
        __syncthreads();
        if (kt + 2 < NT) { g2_fill(sbase, row_base, wb, cgo, kt+2, (kt+2)%3, tid); CP_COMMIT(); }

        unsigned st = sbase + (unsigned)(kt % 3) * G2_STG;
        #pragma unroll
        for (int kk = 0; kk < 4; kk++) {
            unsigned af[2][4];
            #pragma unroll
            for (int mi = 0; mi < 2; mi++)
                ldsm4(af[mi][0], af[mi][1], af[mi][2], af[mi][3],
                      ldsm_addr(st, m0 + mi*16 + arow, ahalf, kk));
            #pragma unroll
            for (int nf = 0; nf < 4; nf++) {
                unsigned b0, b1, b2, b3;
                int brow = n0 + nf*16 + arow;
                ldsm4(b0, b1, b2, b3, ldsm_addr(st + G2_BOFF, brow, ahalf, kk));
                #pragma unroll
                for (int mi = 0; mi < 2; mi++) {
                    mma16816h(acc[mi][nf*2 + 0], af[mi], b0, b2);
                    mma16816h(acc[mi][nf*2 + 1], af[mi], b1, b3);
                }
            }
        }
    }

    __syncthreads();
    float sc = __ldg(w2_scale + e);
    float* sC = (float*)smc;
    int qrow = lane >> 2, qc2 = (lane & 3) * 2;
    #pragma unroll
    for (int mi = 0; mi < 2; mi++)
        #pragma unroll
        for (int half = 0; half < 2; half++) {
            int r = m0 + mi*16 + half*8 + qrow;
            int ei = half*2;
            #pragma unroll
            for (int j = 0; j < 8; j++) {
                float2 v;
                v.x = acc[mi][j][ei]   * sc;
                v.y = acc[mi][j][ei+1] * sc;
                *(float2*)(sC + r*G2_PITCH + n0 + j*8 + qc2) = v;
            }
        }
    __syncthreads();
    #pragma unroll
    for (int it = 0; it < 16; it++) {
        int i = tid + it*256;
        int r = i >> 5, c = i & 31;
        if (r < rows) {
            *(float4*)(g_part + (size_t)(row_base + r) * DMODEL + (size_t)cgo*128 + c*4) =
                *(const float4*)(sC + r*G2_PITCH + c*4);
        }
    }
}

// ---------------- launch 5: combine ----------------
__global__ void k_combine(float* __restrict__ out) {
    const int n4 = NTOK*DMODEL/4;
    const float4* part4 = (const float4*)g_part;
    int stride = gridDim.x*blockDim.x;
    int i = blockIdx.x*blockDim.x + threadIdx.x;
    for (; i + stride < n4; i += 2*stride) {
        #pragma unroll
        for (int u = 0; u < 2; u++) {
            int j = i + u*stride;
            int t  = j >> 9;
            int c4 = j & 511;
            float w0 = g_cw[2*t], w1 = g_cw[2*t+1];
            int p0 = g_pos[2*t], p1 = g_pos[2*t+1];
            float4 a = part4[(size_t)p0*512 + c4];
            float4 b = part4[(size_t)p1*512 + c4];
            float4 o;
            o.x = w0*a.x + w1*b.x;
            o.y = w0*a.y + w1*b.y;
            o.z = w0*a.z + w1*b.z;
            o.w = w0*a.w + w1*b.w;
            ((float4*)out)[j] = o;
        }
    }
    for (; i < n4; i += stride) {
        int t  = i >> 9;
        int c4 = i & 511;
        float w0 = g_cw[2*t], w1 = g_cw[2*t+1];
        int p0 = g_pos[2*t], p1 = g_pos[2*t+1];
        float4 a = part4[(size_t)p0*512 + c4];
        float4 b = part4[(size_t)p1*512 + c4];
        float4 o;
        o.x = w0*a.x + w1*b.x;
        o.y = w0*a.y + w1*b.y;
        o.z = w0*a.z + w1*b.z;
        o.w = w0*a.w + w1*b.w;
        ((float4*)out)[i] = o;
    }
}

// ---------------- launch ----------------
extern "C" void kernel_launch(void* const* d_in, const int* in_sizes, int n_in,
                              void* d_out, int out_size) {
    const float* x      = (const float*)d_in[0];
    const float* gating = (const float*)d_in[1];
    const float* w13q   = (const float*)d_in[2];
    const float* w13s   = (const float*)d_in[3];
    const float* w2q    = (const float*)d_in[4];
    const float* w2s    = (const float*)d_in[5];
    float* out = (float*)d_out;

    cudaFuncSetAttribute(k_gemm1, cudaFuncAttributeMaxDynamicSharedMemorySize, G1_SMEM);
    cudaFuncSetAttribute(k_gemm2, cudaFuncAttributeMaxDynamicSharedMemorySize, G2_SMEM);

    k_amax<<<AMAX_BLOCKS, 256>>>((const float4*)x, NTOK*DMODEL/4);
    k_quant<<<512, 256>>>((const float4*)x, NTOK*DMODEL/16);
    k_fuse<<<FUSE_GRID, 256>>>(gating, (const float4*)w13q, (const float4*)w2q);

    dim3 gg1(32, MAXTILES);
    k_gemm1<<<gg1, 256, G1_SMEM>>>(w13s);          // launch index 3 -> profiled
    dim3 gg2(16, MAXTILES);
    k_gemm2<<<gg2, 256, G2_SMEM>>>(w2s);

    k_combine<<<1184, 256>>>(out);
}